// round 6
// baseline (speedup 1.0000x reference)
#include <cuda_runtime.h>
#include <cuda_bf16.h>
#include <cstdint>

// Problem constants
#define C_IN    256
#define S_SEQ   90
#define K_DIM   180
#define B_BATCH 4096
#define N_OUT   2086
#define MT      (B_BATCH / 128)        // 32 m-tile images
#define NT      ((N_OUT + 127) / 128)  // 17 n-tile images
#define PITCHB  208                    // bytes per row (16B aligned, conflict-free ldmatrix)
#define TILE_B  (128 * PITCHB)         // 26624 bytes per int8 tile image

// int8 hi/lo tile images, [tile][row][k byte], pitch 208.
// k in [180,192) must stay ZERO (zero-init, never written): GEMM consumes k<192.
__device__ __align__(16) signed char g_Ah[MT * TILE_B];
__device__ __align__(16) signed char g_Al[MT * TILE_B];
__device__ __align__(16) signed char g_Bh[NT * TILE_B];
__device__ __align__(16) signed char g_Bl[NT * TILE_B];
__device__ float g_sA[B_BATCH];        // per-row scale of A
__device__ float g_sB[NT * 128];       // per-row scale of B (pad entries unused)

// quantize v -> hi + lo/128 (hi,lo int8), given inv_sc = 127/amax
__device__ __forceinline__ void qstore(signed char* hi, signed char* lo,
                                       size_t idx, float v, float inv_sc) {
    float q = v * inv_sc;                 // |q| <= 127
    float h = rintf(q);
    float l2 = rintf((q - h) * 128.f);    // in [-64, 64]
    hi[idx] = (signed char)(int)h;
    lo[idx] = (signed char)(int)l2;
}

// ---------------------------------------------------------------------------
// prep_b: one block per output row n. Row amax -> scale -> int8 hi/lo.
// ---------------------------------------------------------------------------
__global__ __launch_bounds__(96) void prep_b_kernel(const float* __restrict__ fc_w) {
    __shared__ float spart[3];
    __shared__ float ssc;
    const int n = blockIdx.x;
    const int t = threadIdx.x;

    float w0 = 0.f, w1 = 0.f;
    if (t < S_SEQ) {
        w0 = fc_w[n * K_DIM + t];
        w1 = fc_w[n * K_DIM + S_SEQ + t];
    }
    float mx = fmaxf(fabsf(w0), fabsf(w1));
    for (int o = 16; o > 0; o >>= 1)
        mx = fmaxf(mx, __shfl_xor_sync(0xffffffffu, mx, o));
    if ((t & 31) == 0) spart[t >> 5] = mx;
    __syncthreads();
    if (t == 0) {
        float m = fmaxf(spart[0], fmaxf(spart[1], spart[2]));
        float sc = fmaxf(m, 1e-30f) / 127.f;
        ssc = sc;
        g_sB[n] = sc;
    }
    __syncthreads();
    if (t < S_SEQ) {
        const float inv = 1.f / ssc;
        size_t base = (size_t)(n >> 7) * TILE_B + (size_t)(n & 127) * PITCHB;
        qstore(g_Bh, g_Bl, base + t,         w0, inv);
        qstore(g_Bh, g_Bl, base + S_SEQ + t, w1, inv);
    }
}

// ---------------------------------------------------------------------------
// head: conv1x1 + BN + attention(head_dim=1) + out_proj -> int8 hi/lo A row.
// 384 threads (R4-proven shape): thread (cc,s) does 64 channels; 4-way reduce.
// ---------------------------------------------------------------------------
__global__ __launch_bounds__(384) void head_kernel(
    const float* __restrict__ x,
    const float* __restrict__ conv_w,
    const float* __restrict__ bn_gamma, const float* __restrict__ bn_beta,
    const float* __restrict__ bn_mean,  const float* __restrict__ bn_var,
    const float* __restrict__ in_proj_w, const float* __restrict__ in_proj_b,
    const float* __restrict__ out_proj_w, const float* __restrict__ out_proj_b)
{
    __shared__ float sw0[C_IN], sw1[C_IN];
    __shared__ float part0[4][96], part1[4][96];
    __shared__ float sk0[S_SEQ], sk1[S_SEQ], sv0[S_SEQ], sv1[S_SEQ];
    __shared__ float sred[4];
    __shared__ float spart[3];
    __shared__ float ssc;

    const int b   = blockIdx.x;
    const int tid = threadIdx.x;
    const int cc  = tid / 96;
    const int s   = tid - cc * 96;

    for (int i = tid; i < C_IN; i += 384) {
        sw0[i] = conv_w[i];
        sw1[i] = conv_w[C_IN + i];
    }
    __syncthreads();

    {
        float a0 = 0.f, a1 = 0.f;
        if (s < S_SEQ) {
            const float* xb = x + (size_t)b * (C_IN * S_SEQ) + cc * (64 * S_SEQ) + s;
            const float* w0 = sw0 + cc * 64;
            const float* w1 = sw1 + cc * 64;
#pragma unroll 16
            for (int c = 0; c < 64; ++c) {
                float xv = __ldg(xb + c * S_SEQ);
                a0 = fmaf(w0[c], xv, a0);
                a1 = fmaf(w1[c], xv, a1);
            }
        }
        part0[cc][s] = a0;
        part1[cc][s] = a1;
    }
    __syncthreads();

    float q0 = 0.f, q1 = 0.f;
    if (tid < S_SEQ) {
        float a0 = part0[0][tid] + part0[1][tid] + part0[2][tid] + part0[3][tid];
        float a1 = part1[0][tid] + part1[1][tid] + part1[2][tid] + part1[3][tid];
        float s0 = bn_gamma[0] * rsqrtf(bn_var[0] + 1e-5f);
        float s1 = bn_gamma[1] * rsqrtf(bn_var[1] + 1e-5f);
        float y0 = fmaf(a0, s0, bn_beta[0] - bn_mean[0] * s0);
        float y1 = fmaf(a1, s1, bn_beta[1] - bn_mean[1] * s1);
        q0       = fmaf(y0, in_proj_w[0],  fmaf(y1, in_proj_w[1],  in_proj_b[0]));
        q1       = fmaf(y0, in_proj_w[2],  fmaf(y1, in_proj_w[3],  in_proj_b[1]));
        sk0[tid] = fmaf(y0, in_proj_w[4],  fmaf(y1, in_proj_w[5],  in_proj_b[2]));
        sk1[tid] = fmaf(y0, in_proj_w[6],  fmaf(y1, in_proj_w[7],  in_proj_b[3]));
        sv0[tid] = fmaf(y0, in_proj_w[8],  fmaf(y1, in_proj_w[9],  in_proj_b[4]));
        sv1[tid] = fmaf(y0, in_proj_w[10], fmaf(y1, in_proj_w[11], in_proj_b[5]));
    }
    __syncthreads();

    if (tid < 64) {
        int h = tid >> 5, lane = tid & 31;
        const float* kk = h ? sk1 : sk0;
        float mx = -3.4e38f, mn = 3.4e38f;
        for (int j = lane; j < S_SEQ; j += 32) {
            float kv = kk[j];
            mx = fmaxf(mx, kv);
            mn = fminf(mn, kv);
        }
        for (int o = 16; o > 0; o >>= 1) {
            mx = fmaxf(mx, __shfl_xor_sync(0xffffffffu, mx, o));
            mn = fminf(mn, __shfl_xor_sync(0xffffffffu, mn, o));
        }
        if (lane == 0) { sred[h * 2] = mx; sred[h * 2 + 1] = mn; }
    }
    __syncthreads();

    float f0 = 0.f, f1 = 0.f;
    if (tid < S_SEQ) {
        float m0 = fmaxf(q0 * sred[0], q0 * sred[1]);
        float m1 = fmaxf(q1 * sred[2], q1 * sred[3]);
        float d0 = 0.f, n0 = 0.f, d1 = 0.f, n1 = 0.f;
#pragma unroll 5
        for (int j = 0; j < S_SEQ; ++j) {
            float e0 = __expf(fmaf(q0, sk0[j], -m0));
            float e1 = __expf(fmaf(q1, sk1[j], -m1));
            d0 += e0; n0 = fmaf(e0, sv0[j], n0);
            d1 += e1; n1 = fmaf(e1, sv1[j], n1);
        }
        float o0 = n0 / d0, o1 = n1 / d1;
        f0 = fmaf(o0, out_proj_w[0], fmaf(o1, out_proj_w[1], out_proj_b[0]));
        f1 = fmaf(o0, out_proj_w[2], fmaf(o1, out_proj_w[3], out_proj_b[1]));
    }

    // block amax over the 180 row values (warps 0-2 fully active)
    if (tid < 96) {
        float mx = (tid < S_SEQ) ? fmaxf(fabsf(f0), fabsf(f1)) : 0.f;
        for (int o = 16; o > 0; o >>= 1)
            mx = fmaxf(mx, __shfl_xor_sync(0xffffffffu, mx, o));
        if ((tid & 31) == 0) spart[tid >> 5] = mx;
    }
    __syncthreads();
    if (tid == 0) {
        float m = fmaxf(spart[0], fmaxf(spart[1], spart[2]));
        float sc = fmaxf(m, 1e-30f) / 127.f;
        ssc = sc;
        g_sA[b] = sc;
    }
    __syncthreads();

    if (tid < S_SEQ) {
        const float inv = 1.f / ssc;
        size_t base = (size_t)(b >> 7) * TILE_B + (size_t)(b & 127) * PITCHB;
        qstore(g_Ah, g_Al, base + tid,         f0, inv);
        qstore(g_Ah, g_Al, base + S_SEQ + tid, f1, inv);
    }
}

// ---------------------------------------------------------------------------
// FC GEMM: int8 mma m16n8k32, dual accumulator (hh -> acc1, hl+lh -> acc2).
// Grid (17, 64), CTA tile 64m x 128n, 256 threads, warp tile 32x32, 2 CTAs/SM.
// ---------------------------------------------------------------------------
#define OFF_BH 0
#define OFF_BL 26624
#define OFF_AH 53248
#define OFF_AL 66560
#define SMEM_FC 79872

__device__ __forceinline__ uint32_t smem_u32(const void* p) {
    uint32_t a;
    asm("{ .reg .u64 t; cvta.to.shared.u64 t, %1; cvt.u32.u64 %0, t; }"
        : "=r"(a) : "l"(p));
    return a;
}

#define CP16(dst, src)                                                         \
    asm volatile("cp.async.cg.shared.global [%0], [%1], 16;"                   \
                 :: "r"(dst), "l"(src))

#define LDSM4(r, addr)                                                         \
    asm volatile("ldmatrix.sync.aligned.m8n8.x4.shared.b16 {%0,%1,%2,%3}, [%4];" \
                 : "=r"((r)[0]), "=r"((r)[1]), "=r"((r)[2]), "=r"((r)[3])      \
                 : "r"(addr))

#define IMMA(c, a, b0v, b1v)                                                   \
    asm volatile(                                                              \
        "mma.sync.aligned.m16n8k32.row.col.s32.s8.s8.s32 "                     \
        "{%0,%1,%2,%3}, {%4,%5,%6,%7}, {%8,%9}, {%0,%1,%2,%3};"                \
        : "+r"((c)[0]), "+r"((c)[1]), "+r"((c)[2]), "+r"((c)[3])               \
        : "r"((a)[0]), "r"((a)[1]), "r"((a)[2]), "r"((a)[3]),                  \
          "r"(b0v), "r"(b1v))

__global__ __launch_bounds__(256, 2) void fc_mma_kernel(
    const float* __restrict__ fc_b, float* __restrict__ out)
{
    extern __shared__ char sm[];
    const uint32_t sb = smem_u32(sm);
    const int tid = threadIdx.x;
    const int wid = tid >> 5;
    const int l   = tid & 31;
    const int nt = blockIdx.x;          // 0..16
    const int mg = blockIdx.y;          // 0..63 (64-row m groups)
    const int n0 = nt * 128;

    // Stage: B tile (hi+lo) 2x26624B, A half-tile (hi+lo) 2x13312B
    {
        const float4* gBh = (const float4*)(g_Bh + (size_t)nt * TILE_B);
        const float4* gBl = (const float4*)(g_Bl + (size_t)nt * TILE_B);
        for (int i = tid; i < 1664; i += 256) {
            CP16(sb + OFF_BH + i * 16, gBh + i);
            CP16(sb + OFF_BL + i * 16, gBl + i);
        }
        const float4* gAh = (const float4*)(g_Ah + (size_t)mg * (64 * PITCHB));
        const float4* gAl = (const float4*)(g_Al + (size_t)mg * (64 * PITCHB));
        for (int i = tid; i < 832; i += 256) {
            CP16(sb + OFF_AH + i * 16, gAh + i);
            CP16(sb + OFF_AL + i * 16, gAl + i);
        }
        asm volatile("cp.async.commit_group;" ::: "memory");
    }

    const int wm = wid & 1;        // 2 x 32 m-rows
    const int wn = wid >> 1;       // 4 x 32 n-cols

    const uint32_t aoff = (uint32_t)((wm * 32 + (l & 15)) * PITCHB
                                     + ((l >> 4) & 1) * 16);
    const uint32_t boff = (uint32_t)((wn * 32 + (l & 7) + ((l >> 4) & 1) * 8) * PITCHB
                                     + ((l >> 3) & 1) * 16);

    int acc1[2][4][4], acc2[2][4][4];
#pragma unroll
    for (int mi = 0; mi < 2; ++mi)
#pragma unroll
        for (int nj = 0; nj < 4; ++nj)
#pragma unroll
            for (int r = 0; r < 4; ++r) { acc1[mi][nj][r] = 0; acc2[mi][nj][r] = 0; }

    asm volatile("cp.async.wait_group 0;" ::: "memory");
    __syncthreads();

#pragma unroll
    for (int ks = 0; ks < 6; ++ks) {
        const uint32_t ko = ks * 32;
        uint32_t ah[2][4], alr[2][4], bh[2][4], blr[2][4];
        LDSM4(ah[0],  sb + OFF_AH + aoff + ko);
        LDSM4(ah[1],  sb + OFF_AH + aoff + 16 * PITCHB + ko);
        LDSM4(alr[0], sb + OFF_AL + aoff + ko);
        LDSM4(alr[1], sb + OFF_AL + aoff + 16 * PITCHB + ko);
        LDSM4(bh[0],  sb + OFF_BH + boff + ko);
        LDSM4(bh[1],  sb + OFF_BH + boff + 16 * PITCHB + ko);
        LDSM4(blr[0], sb + OFF_BL + boff + ko);
        LDSM4(blr[1], sb + OFF_BL + boff + 16 * PITCHB + ko);
#pragma unroll
        for (int mi = 0; mi < 2; ++mi) {
            IMMA(acc1[mi][0], ah[mi],  bh[0][0],  bh[0][1]);
            IMMA(acc1[mi][1], ah[mi],  bh[0][2],  bh[0][3]);
            IMMA(acc1[mi][2], ah[mi],  bh[1][0],  bh[1][1]);
            IMMA(acc1[mi][3], ah[mi],  bh[1][2],  bh[1][3]);
            IMMA(acc2[mi][0], ah[mi],  blr[0][0], blr[0][1]);
            IMMA(acc2[mi][1], ah[mi],  blr[0][2], blr[0][3]);
            IMMA(acc2[mi][2], ah[mi],  blr[1][0], blr[1][1]);
            IMMA(acc2[mi][3], ah[mi],  blr[1][2], blr[1][3]);
            IMMA(acc2[mi][0], alr[mi], bh[0][0],  bh[0][1]);
            IMMA(acc2[mi][1], alr[mi], bh[0][2],  bh[0][3]);
            IMMA(acc2[mi][2], alr[mi], bh[1][0],  bh[1][1]);
            IMMA(acc2[mi][3], alr[mi], bh[1][2],  bh[1][3]);
        }
    }

    // Epilogue: out = sA[m]*sB[n]*(acc1 + acc2/128) + bias
    const int nvalid = N_OUT - n0;
    const int mrow = mg * 64 + wm * 32 + (l >> 2);
    float sa0 = g_sA[mrow];
    float sa1 = g_sA[mrow + 8];
    float sa2 = g_sA[mrow + 16];
    float sa3 = g_sA[mrow + 24];

#pragma unroll
    for (int nj = 0; nj < 4; ++nj) {
        const int n = wn * 32 + nj * 8 + (l & 3) * 2;
        if (n < nvalid) {
            const float sb0 = g_sB[n0 + n];
            const float sb1 = g_sB[n0 + n + 1];
            const float b0 = __ldg(fc_b + n0 + n);
            const float b1 = __ldg(fc_b + n0 + n + 1);
#pragma unroll
            for (int mi = 0; mi < 2; ++mi) {
                const float sA0 = mi ? sa2 : sa0;
                const float sA1 = mi ? sa3 : sa1;
                const int m = mg * 64 + wm * 32 + mi * 16 + (l >> 2);
                float* p0 = out + (size_t)m * N_OUT + n0 + n;
                float* p1 = out + (size_t)(m + 8) * N_OUT + n0 + n;
                float v00 = sA0 * sb0 * ((float)acc1[mi][nj][0]
                           + 0.0078125f * (float)acc2[mi][nj][0]) + b0;
                float v01 = sA0 * sb1 * ((float)acc1[mi][nj][1]
                           + 0.0078125f * (float)acc2[mi][nj][1]) + b1;
                float v10 = sA1 * sb0 * ((float)acc1[mi][nj][2]
                           + 0.0078125f * (float)acc2[mi][nj][2]) + b0;
                float v11 = sA1 * sb1 * ((float)acc1[mi][nj][3]
                           + 0.0078125f * (float)acc2[mi][nj][3]) + b1;
                *(float2*)p0 = make_float2(v00, v01);
                *(float2*)p1 = make_float2(v10, v11);
            }
        }
    }
}

// ---------------------------------------------------------------------------
extern "C" void kernel_launch(void* const* d_in, const int* in_sizes, int n_in,
                              void* d_out, int out_size) {
    const float* x          = (const float*)d_in[0];
    const float* conv_w     = (const float*)d_in[1];
    const float* bn_gamma   = (const float*)d_in[2];
    const float* bn_beta    = (const float*)d_in[3];
    const float* bn_mean    = (const float*)d_in[4];
    const float* bn_var     = (const float*)d_in[5];
    const float* in_proj_w  = (const float*)d_in[6];
    const float* in_proj_b  = (const float*)d_in[7];
    const float* out_proj_w = (const float*)d_in[8];
    const float* out_proj_b = (const float*)d_in[9];
    const float* fc_w       = (const float*)d_in[10];
    const float* fc_b       = (const float*)d_in[11];
    float* out = (float*)d_out;

    cudaFuncSetAttribute(fc_mma_kernel,
                         cudaFuncAttributeMaxDynamicSharedMemorySize, SMEM_FC);

    prep_b_kernel<<<N_OUT, 96>>>(fc_w);
    head_kernel<<<B_BATCH, 384>>>(x, conv_w, bn_gamma, bn_beta, bn_mean, bn_var,
                                  in_proj_w, in_proj_b, out_proj_w, out_proj_b);
    fc_mma_kernel<<<dim3(NT, 64), 256, SMEM_FC>>>(fc_b, out);
}

// round 7
// speedup vs baseline: 1.5647x; 1.5647x over previous
#include <cuda_runtime.h>
#include <cuda_fp16.h>
#include <cstdint>

// Problem constants
#define C_IN    256
#define S_SEQ   90
#define K_DIM   180
#define B_BATCH 4096
#define N_OUT   2086
#define MT      (B_BATCH / 128)        // 32 m-tile images (128 rows each)
#define NT      ((N_OUT + 127) / 128)  // 17 n-tile images
#define PITCH   200                    // row pitch in fp16 elems (400B, conflict-free ldmatrix)
#define TILE_E  (128 * PITCH)          // elems per 128-row tile image

// Tile images: [row][k] fp16, pitch 200. k in [180,200) stays ZERO (zero-init,
// never written); the GEMM consumes k in [0,192).
__device__ __align__(16) __half g_Ahi[MT * TILE_E];
__device__ __align__(16) __half g_Alo[MT * TILE_E];
__device__ __align__(16) __half g_Bhi[NT * TILE_E];

// ---------------------------------------------------------------------------
// prep_b: fc_w [2086,180] -> fp16 B tile image (single term; B quantization
// error ~2^-12 is the dominant, accepted error of the whole pipeline)
// ---------------------------------------------------------------------------
__global__ void prep_b_kernel(const float* __restrict__ fc_w) {
    int i = blockIdx.x * 256 + threadIdx.x;
    if (i >= N_OUT * K_DIM) return;
    int n = i / K_DIM;
    int k = i - n * K_DIM;
    size_t idx = (size_t)(n >> 7) * TILE_E + (n & 127) * PITCH + k;
    g_Bhi[idx] = __float2half(fc_w[i]);
}

// ---------------------------------------------------------------------------
// head: conv1x1 + BN + attention(head_dim=1) + out_proj -> fp16 hi/lo A tiles
// 384 threads (R4-proven): thread (cc,s) does 64 channels; 4-way smem reduce.
// ---------------------------------------------------------------------------
__global__ __launch_bounds__(384) void head_kernel(
    const float* __restrict__ x,
    const float* __restrict__ conv_w,
    const float* __restrict__ bn_gamma, const float* __restrict__ bn_beta,
    const float* __restrict__ bn_mean,  const float* __restrict__ bn_var,
    const float* __restrict__ in_proj_w, const float* __restrict__ in_proj_b,
    const float* __restrict__ out_proj_w, const float* __restrict__ out_proj_b)
{
    __shared__ float sw0[C_IN], sw1[C_IN];
    __shared__ float part0[4][96], part1[4][96];
    __shared__ float sk0[S_SEQ], sk1[S_SEQ], sv0[S_SEQ], sv1[S_SEQ];
    __shared__ float sred[4];

    const int b   = blockIdx.x;
    const int tid = threadIdx.x;
    const int cc  = tid / 96;
    const int s   = tid - cc * 96;

    for (int i = tid; i < C_IN; i += 384) {
        sw0[i] = conv_w[i];
        sw1[i] = conv_w[C_IN + i];
    }
    __syncthreads();

    {
        float a0 = 0.f, a1 = 0.f;
        if (s < S_SEQ) {
            const float* xb = x + (size_t)b * (C_IN * S_SEQ) + cc * (64 * S_SEQ) + s;
            const float* w0 = sw0 + cc * 64;
            const float* w1 = sw1 + cc * 64;
#pragma unroll 16
            for (int c = 0; c < 64; ++c) {
                float xv = __ldg(xb + c * S_SEQ);
                a0 = fmaf(w0[c], xv, a0);
                a1 = fmaf(w1[c], xv, a1);
            }
        }
        part0[cc][s] = a0;
        part1[cc][s] = a1;
    }
    __syncthreads();

    float q0 = 0.f, q1 = 0.f;
    if (tid < S_SEQ) {
        float a0 = part0[0][tid] + part0[1][tid] + part0[2][tid] + part0[3][tid];
        float a1 = part1[0][tid] + part1[1][tid] + part1[2][tid] + part1[3][tid];
        float s0 = bn_gamma[0] * rsqrtf(bn_var[0] + 1e-5f);
        float s1 = bn_gamma[1] * rsqrtf(bn_var[1] + 1e-5f);
        float y0 = fmaf(a0, s0, bn_beta[0] - bn_mean[0] * s0);
        float y1 = fmaf(a1, s1, bn_beta[1] - bn_mean[1] * s1);
        q0       = fmaf(y0, in_proj_w[0],  fmaf(y1, in_proj_w[1],  in_proj_b[0]));
        q1       = fmaf(y0, in_proj_w[2],  fmaf(y1, in_proj_w[3],  in_proj_b[1]));
        sk0[tid] = fmaf(y0, in_proj_w[4],  fmaf(y1, in_proj_w[5],  in_proj_b[2]));
        sk1[tid] = fmaf(y0, in_proj_w[6],  fmaf(y1, in_proj_w[7],  in_proj_b[3]));
        sv0[tid] = fmaf(y0, in_proj_w[8],  fmaf(y1, in_proj_w[9],  in_proj_b[4]));
        sv1[tid] = fmaf(y0, in_proj_w[10], fmaf(y1, in_proj_w[11], in_proj_b[5]));
    }
    __syncthreads();

    if (tid < 64) {
        int h = tid >> 5, lane = tid & 31;
        const float* kk = h ? sk1 : sk0;
        float mx = -3.4e38f, mn = 3.4e38f;
        for (int j = lane; j < S_SEQ; j += 32) {
            float kv = kk[j];
            mx = fmaxf(mx, kv);
            mn = fminf(mn, kv);
        }
        for (int o = 16; o > 0; o >>= 1) {
            mx = fmaxf(mx, __shfl_xor_sync(0xffffffffu, mx, o));
            mn = fminf(mn, __shfl_xor_sync(0xffffffffu, mn, o));
        }
        if (lane == 0) { sred[h * 2] = mx; sred[h * 2 + 1] = mn; }
    }
    __syncthreads();

    if (tid < S_SEQ) {
        float m0 = fmaxf(q0 * sred[0], q0 * sred[1]);
        float m1 = fmaxf(q1 * sred[2], q1 * sred[3]);
        float d0 = 0.f, n0 = 0.f, d1 = 0.f, n1 = 0.f;
#pragma unroll 5
        for (int j = 0; j < S_SEQ; ++j) {
            float e0 = __expf(fmaf(q0, sk0[j], -m0));
            float e1 = __expf(fmaf(q1, sk1[j], -m1));
            d0 += e0; n0 = fmaf(e0, sv0[j], n0);
            d1 += e1; n1 = fmaf(e1, sv1[j], n1);
        }
        float o0 = n0 / d0, o1 = n1 / d1;
        float f0 = fmaf(o0, out_proj_w[0], fmaf(o1, out_proj_w[1], out_proj_b[0]));
        float f1 = fmaf(o0, out_proj_w[2], fmaf(o1, out_proj_w[3], out_proj_b[1]));
        size_t base = (size_t)(b >> 7) * TILE_E + (size_t)(b & 127) * PITCH;
        // split A: hi + lo (exact to ~2^-24)
        __half h0 = __float2half(f0);
        __half h1 = __float2half(f1);
        g_Ahi[base + tid]         = h0;
        g_Ahi[base + S_SEQ + tid] = h1;
        g_Alo[base + tid]         = __float2half(f0 - __half2float(h0));
        g_Alo[base + S_SEQ + tid] = __float2half(f1 - __half2float(h1));
    }
}

// ---------------------------------------------------------------------------
// FC GEMM: fp16 mma m16n8k16, 2 terms (ah*bh + al*bh), fp32 accum.
// Grid (17, 64): CTA tile 64m x 128n, 256 threads (8 warps, 32x32 warp tile),
// 102.4KB smem -> 2 CTAs/SM for cross-CTA stage/compute overlap.
// ---------------------------------------------------------------------------
#define OFF_AH 0          // 25600 B (64 rows x 400B)
#define OFF_AL 25600      // 25600 B
#define OFF_BH 51200      // 51200 B (128 rows x 400B)
#define SMEM_FC 102400

__device__ __forceinline__ uint32_t smem_u32(const void* p) {
    uint32_t a;
    asm("{ .reg .u64 t; cvta.to.shared.u64 t, %1; cvt.u32.u64 %0, t; }"
        : "=r"(a) : "l"(p));
    return a;
}

#define CP16(dst, src)                                                         \
    asm volatile("cp.async.cg.shared.global [%0], [%1], 16;"                   \
                 :: "r"(dst), "l"(src))

#define LDSM4(r, addr)                                                         \
    asm volatile("ldmatrix.sync.aligned.m8n8.x4.shared.b16 {%0,%1,%2,%3}, [%4];" \
                 : "=r"((r)[0]), "=r"((r)[1]), "=r"((r)[2]), "=r"((r)[3])      \
                 : "r"(addr))

#define MMA16816(c, a, b0v, b1v)                                               \
    asm volatile(                                                              \
        "mma.sync.aligned.m16n8k16.row.col.f32.f16.f16.f32 "                   \
        "{%0,%1,%2,%3}, {%4,%5,%6,%7}, {%8,%9}, {%0,%1,%2,%3};"                \
        : "+f"((c)[0]), "+f"((c)[1]), "+f"((c)[2]), "+f"((c)[3])               \
        : "r"((a)[0]), "r"((a)[1]), "r"((a)[2]), "r"((a)[3]),                  \
          "r"(b0v), "r"(b1v))

__global__ __launch_bounds__(256, 2) void fc_mma_kernel(
    const float* __restrict__ fc_b, float* __restrict__ out)
{
    extern __shared__ char sm[];
    const uint32_t sb = smem_u32(sm);
    const int tid = threadIdx.x;
    const int wid = tid >> 5;
    const int l   = tid & 31;
    const int nt = blockIdx.x;          // 0..16
    const int mg = blockIdx.y;          // 0..63 (64-row m-groups)
    const int n0 = nt * 128;

    // Stage: group 0 = A-hi + B-hi (term 0 inputs), group 1 = A-lo
    {
        const float4* gAh = (const float4*)(g_Ahi + (size_t)(mg >> 1) * TILE_E
                                            + (mg & 1) * (64 * PITCH));
        const float4* gBh = (const float4*)(g_Bhi + (size_t)nt * TILE_E);
        for (int i = tid; i < 1600; i += 256)
            CP16(sb + OFF_AH + i * 16, gAh + i);
        for (int i = tid; i < 3200; i += 256)
            CP16(sb + OFF_BH + i * 16, gBh + i);
        asm volatile("cp.async.commit_group;" ::: "memory");
        const float4* gAl = (const float4*)(g_Alo + (size_t)(mg >> 1) * TILE_E
                                            + (mg & 1) * (64 * PITCH));
        for (int i = tid; i < 1600; i += 256)
            CP16(sb + OFF_AL + i * 16, gAl + i);
        asm volatile("cp.async.commit_group;" ::: "memory");
    }

    const int wm = wid & 1;        // 2 x 32 m-rows
    const int wn = wid >> 1;       // 4 x 32 n-cols

    const uint32_t aoff = (uint32_t)((wm * 32 + (l & 15)) * 400 + ((l >> 4) & 1) * 16);
    const uint32_t boff = (uint32_t)((wn * 32 + (l & 7) + ((l >> 4) & 1) * 8) * 400
                                     + ((l >> 3) & 1) * 16);

    float acc[2][4][4];
#pragma unroll
    for (int mi = 0; mi < 2; ++mi)
#pragma unroll
        for (int nj = 0; nj < 4; ++nj)
#pragma unroll
            for (int r = 0; r < 4; ++r) acc[mi][nj][r] = 0.f;

    // ---- term 0: ah * bh (A-lo still in flight) ----
    asm volatile("cp.async.wait_group 1;" ::: "memory");
    __syncthreads();
#pragma unroll 4
    for (int ks = 0; ks < 12; ++ks) {
        const uint32_t ko = ks * 32;
        uint32_t a[2][4], bq0[4], bq1[4];
        LDSM4(a[0], sb + OFF_AH + aoff + ko);
        LDSM4(a[1], sb + OFF_AH + aoff + 6400 + ko);
        LDSM4(bq0, sb + OFF_BH + boff + ko);
        LDSM4(bq1, sb + OFF_BH + boff + 6400 + ko);
#pragma unroll
        for (int mi = 0; mi < 2; ++mi) {
            MMA16816(acc[mi][0], a[mi], bq0[0], bq0[1]);
            MMA16816(acc[mi][1], a[mi], bq0[2], bq0[3]);
            MMA16816(acc[mi][2], a[mi], bq1[0], bq1[1]);
            MMA16816(acc[mi][3], a[mi], bq1[2], bq1[3]);
        }
    }

    // ---- term 1: al * bh ----
    asm volatile("cp.async.wait_group 0;" ::: "memory");
    __syncthreads();
#pragma unroll 4
    for (int ks = 0; ks < 12; ++ks) {
        const uint32_t ko = ks * 32;
        uint32_t a[2][4], bq0[4], bq1[4];
        LDSM4(a[0], sb + OFF_AL + aoff + ko);
        LDSM4(a[1], sb + OFF_AL + aoff + 6400 + ko);
        LDSM4(bq0, sb + OFF_BH + boff + ko);
        LDSM4(bq1, sb + OFF_BH + boff + 6400 + ko);
#pragma unroll
        for (int mi = 0; mi < 2; ++mi) {
            MMA16816(acc[mi][0], a[mi], bq0[0], bq0[1]);
            MMA16816(acc[mi][1], a[mi], bq0[2], bq0[3]);
            MMA16816(acc[mi][2], a[mi], bq1[0], bq1[1]);
            MMA16816(acc[mi][3], a[mi], bq1[2], bq1[3]);
        }
    }

    // Epilogue: direct stores + bias
    const int nvalid = N_OUT - n0;
#pragma unroll
    for (int nj = 0; nj < 4; ++nj) {
        const int n = wn * 32 + nj * 8 + (l & 3) * 2;
        if (n < nvalid) {
            const float b0 = __ldg(fc_b + n0 + n);
            const float b1 = __ldg(fc_b + n0 + n + 1);
#pragma unroll
            for (int mi = 0; mi < 2; ++mi) {
                const int m = mg * 64 + wm * 32 + mi * 16 + (l >> 2);
                float* p0 = out + (size_t)m * N_OUT + n0 + n;
                float* p1 = out + (size_t)(m + 8) * N_OUT + n0 + n;
                *(float2*)p0 = make_float2(acc[mi][nj][0] + b0, acc[mi][nj][1] + b1);
                *(float2*)p1 = make_float2(acc[mi][nj][2] + b0, acc[mi][nj][3] + b1);
            }
        }
    }
}

// ---------------------------------------------------------------------------
extern "C" void kernel_launch(void* const* d_in, const int* in_sizes, int n_in,
                              void* d_out, int out_size) {
    const float* x          = (const float*)d_in[0];
    const float* conv_w     = (const float*)d_in[1];
    const float* bn_gamma   = (const float*)d_in[2];
    const float* bn_beta    = (const float*)d_in[3];
    const float* bn_mean    = (const float*)d_in[4];
    const float* bn_var     = (const float*)d_in[5];
    const float* in_proj_w  = (const float*)d_in[6];
    const float* in_proj_b  = (const float*)d_in[7];
    const float* out_proj_w = (const float*)d_in[8];
    const float* out_proj_b = (const float*)d_in[9];
    const float* fc_w       = (const float*)d_in[10];
    const float* fc_b       = (const float*)d_in[11];
    float* out = (float*)d_out;

    cudaFuncSetAttribute(fc_mma_kernel,
                         cudaFuncAttributeMaxDynamicSharedMemorySize, SMEM_FC);

    prep_b_kernel<<<(N_OUT * K_DIM + 255) / 256, 256>>>(fc_w);
    head_kernel<<<B_BATCH, 384>>>(x, conv_w, bn_gamma, bn_beta, bn_mean, bn_var,
                                  in_proj_w, in_proj_b, out_proj_w, out_proj_b);
    fc_mma_kernel<<<dim3(NT, 64), 256, SMEM_FC>>>(fc_b, out);
}

// round 8
// speedup vs baseline: 1.6811x; 1.0744x over previous
#include <cuda_runtime.h>
#include <cuda_fp16.h>
#include <cstdint>

// Problem constants
#define C_IN    256
#define S_SEQ   90
#define K_DIM   180
#define B_BATCH 4096
#define N_OUT   2086
#define MT      (B_BATCH / 128)        // 32 m-tile images (128 rows each)
#define NT      ((N_OUT + 127) / 128)  // 17 n-tile images
#define PITCH   200                    // row pitch in fp16 elems (400B, conflict-free ldmatrix)
#define TILE_E  (128 * PITCH)          // elems per 128-row tile image

// Tile images: [row][k] fp16, pitch 200. k in [180,200) stays ZERO (zero-init,
// never written); the GEMM consumes k in [0,192).
__device__ __align__(16) __half g_Ahi[MT * TILE_E];
__device__ __align__(16) __half g_Bhi[NT * TILE_E];

// ---------------------------------------------------------------------------
// prep_b: fc_w [2086,180] -> fp16 B tile image
// ---------------------------------------------------------------------------
__global__ void prep_b_kernel(const float* __restrict__ fc_w) {
    int i = blockIdx.x * 256 + threadIdx.x;
    if (i >= N_OUT * K_DIM) return;
    int n = i / K_DIM;
    int k = i - n * K_DIM;
    size_t idx = (size_t)(n >> 7) * TILE_E + (n & 127) * PITCH + k;
    g_Bhi[idx] = __float2half(fc_w[i]);
}

// ---------------------------------------------------------------------------
// head: conv1x1 + BN + attention(head_dim=1) + out_proj -> fp16 A tiles
// 384 threads (proven shape): thread (cc,s) does 64 channels; 4-way smem reduce.
// ---------------------------------------------------------------------------
__global__ __launch_bounds__(384) void head_kernel(
    const float* __restrict__ x,
    const float* __restrict__ conv_w,
    const float* __restrict__ bn_gamma, const float* __restrict__ bn_beta,
    const float* __restrict__ bn_mean,  const float* __restrict__ bn_var,
    const float* __restrict__ in_proj_w, const float* __restrict__ in_proj_b,
    const float* __restrict__ out_proj_w, const float* __restrict__ out_proj_b)
{
    __shared__ float sw0[C_IN], sw1[C_IN];
    __shared__ float part0[4][96], part1[4][96];
    __shared__ float sk0[S_SEQ], sk1[S_SEQ], sv0[S_SEQ], sv1[S_SEQ];
    __shared__ float sred[4];

    const int b   = blockIdx.x;
    const int tid = threadIdx.x;
    const int cc  = tid / 96;
    const int s   = tid - cc * 96;

    for (int i = tid; i < C_IN; i += 384) {
        sw0[i] = conv_w[i];
        sw1[i] = conv_w[C_IN + i];
    }
    __syncthreads();

    {
        float a0 = 0.f, a1 = 0.f;
        if (s < S_SEQ) {
            const float* xb = x + (size_t)b * (C_IN * S_SEQ) + cc * (64 * S_SEQ) + s;
            const float* w0 = sw0 + cc * 64;
            const float* w1 = sw1 + cc * 64;
#pragma unroll 16
            for (int c = 0; c < 64; ++c) {
                float xv = __ldg(xb + c * S_SEQ);
                a0 = fmaf(w0[c], xv, a0);
                a1 = fmaf(w1[c], xv, a1);
            }
        }
        part0[cc][s] = a0;
        part1[cc][s] = a1;
    }
    __syncthreads();

    float q0 = 0.f, q1 = 0.f;
    if (tid < S_SEQ) {
        float a0 = part0[0][tid] + part0[1][tid] + part0[2][tid] + part0[3][tid];
        float a1 = part1[0][tid] + part1[1][tid] + part1[2][tid] + part1[3][tid];
        float s0 = bn_gamma[0] * rsqrtf(bn_var[0] + 1e-5f);
        float s1 = bn_gamma[1] * rsqrtf(bn_var[1] + 1e-5f);
        float y0 = fmaf(a0, s0, bn_beta[0] - bn_mean[0] * s0);
        float y1 = fmaf(a1, s1, bn_beta[1] - bn_mean[1] * s1);
        q0       = fmaf(y0, in_proj_w[0],  fmaf(y1, in_proj_w[1],  in_proj_b[0]));
        q1       = fmaf(y0, in_proj_w[2],  fmaf(y1, in_proj_w[3],  in_proj_b[1]));
        sk0[tid] = fmaf(y0, in_proj_w[4],  fmaf(y1, in_proj_w[5],  in_proj_b[2]));
        sk1[tid] = fmaf(y0, in_proj_w[6],  fmaf(y1, in_proj_w[7],  in_proj_b[3]));
        sv0[tid] = fmaf(y0, in_proj_w[8],  fmaf(y1, in_proj_w[9],  in_proj_b[4]));
        sv1[tid] = fmaf(y0, in_proj_w[10], fmaf(y1, in_proj_w[11], in_proj_b[5]));
    }
    __syncthreads();

    if (tid < 64) {
        int h = tid >> 5, lane = tid & 31;
        const float* kk = h ? sk1 : sk0;
        float mx = -3.4e38f, mn = 3.4e38f;
        for (int j = lane; j < S_SEQ; j += 32) {
            float kv = kk[j];
            mx = fmaxf(mx, kv);
            mn = fminf(mn, kv);
        }
        for (int o = 16; o > 0; o >>= 1) {
            mx = fmaxf(mx, __shfl_xor_sync(0xffffffffu, mx, o));
            mn = fminf(mn, __shfl_xor_sync(0xffffffffu, mn, o));
        }
        if (lane == 0) { sred[h * 2] = mx; sred[h * 2 + 1] = mn; }
    }
    __syncthreads();

    if (tid < S_SEQ) {
        float m0 = fmaxf(q0 * sred[0], q0 * sred[1]);
        float m1 = fmaxf(q1 * sred[2], q1 * sred[3]);
        float d0 = 0.f, n0 = 0.f, d1 = 0.f, n1 = 0.f;
#pragma unroll 5
        for (int j = 0; j < S_SEQ; ++j) {
            float e0 = __expf(fmaf(q0, sk0[j], -m0));
            float e1 = __expf(fmaf(q1, sk1[j], -m1));
            d0 += e0; n0 = fmaf(e0, sv0[j], n0);
            d1 += e1; n1 = fmaf(e1, sv1[j], n1);
        }
        float o0 = n0 / d0, o1 = n1 / d1;
        float f0 = fmaf(o0, out_proj_w[0], fmaf(o1, out_proj_w[1], out_proj_b[0]));
        float f1 = fmaf(o0, out_proj_w[2], fmaf(o1, out_proj_w[3], out_proj_b[1]));
        size_t base = (size_t)(b >> 7) * TILE_E + (size_t)(b & 127) * PITCH;
        g_Ahi[base + tid]         = __float2half(f0);
        g_Ahi[base + S_SEQ + tid] = __float2half(f1);
    }
}

// ---------------------------------------------------------------------------
// FC GEMM: fp16 mma m16n8k16, single term, fp32 accum.
// Grid (17, 64): CTA tile 64m x 128n, 256 threads (8 warps, 32x32 warp tile),
// 76.8KB smem -> 2 CTAs/SM for cross-CTA stage/compute overlap.
// ---------------------------------------------------------------------------
#define OFF_AH 0          // 25600 B (64 rows x 400B)
#define OFF_BH 25600      // 51200 B (128 rows x 400B)
#define SMEM_FC 76800

__device__ __forceinline__ uint32_t smem_u32(const void* p) {
    uint32_t a;
    asm("{ .reg .u64 t; cvta.to.shared.u64 t, %1; cvt.u32.u64 %0, t; }"
        : "=r"(a) : "l"(p));
    return a;
}

#define CP16(dst, src)                                                         \
    asm volatile("cp.async.cg.shared.global [%0], [%1], 16;"                   \
                 :: "r"(dst), "l"(src))

#define LDSM4(r, addr)                                                         \
    asm volatile("ldmatrix.sync.aligned.m8n8.x4.shared.b16 {%0,%1,%2,%3}, [%4];" \
                 : "=r"((r)[0]), "=r"((r)[1]), "=r"((r)[2]), "=r"((r)[3])      \
                 : "r"(addr))

#define MMA16816(c, a, b0v, b1v)                                               \
    asm volatile(                                                              \
        "mma.sync.aligned.m16n8k16.row.col.f32.f16.f16.f32 "                   \
        "{%0,%1,%2,%3}, {%4,%5,%6,%7}, {%8,%9}, {%0,%1,%2,%3};"                \
        : "+f"((c)[0]), "+f"((c)[1]), "+f"((c)[2]), "+f"((c)[3])               \
        : "r"((a)[0]), "r"((a)[1]), "r"((a)[2]), "r"((a)[3]),                  \
          "r"(b0v), "r"(b1v))

__global__ __launch_bounds__(256, 2) void fc_mma_kernel(
    const float* __restrict__ fc_b, float* __restrict__ out)
{
    extern __shared__ char sm[];
    const uint32_t sb = smem_u32(sm);
    const int tid = threadIdx.x;
    const int wid = tid >> 5;
    const int l   = tid & 31;
    const int nt = blockIdx.x;          // 0..16
    const int mg = blockIdx.y;          // 0..63 (64-row m-groups)
    const int n0 = nt * 128;

    // Stage A + B (one cp.async group)
    {
        const float4* gAh = (const float4*)(g_Ahi + (size_t)(mg >> 1) * TILE_E
                                            + (mg & 1) * (64 * PITCH));
        const float4* gBh = (const float4*)(g_Bhi + (size_t)nt * TILE_E);
        for (int i = tid; i < 1600; i += 256)
            CP16(sb + OFF_AH + i * 16, gAh + i);
        for (int i = tid; i < 3200; i += 256)
            CP16(sb + OFF_BH + i * 16, gBh + i);
        asm volatile("cp.async.commit_group;" ::: "memory");
    }

    const int wm = wid & 1;        // 2 x 32 m-rows
    const int wn = wid >> 1;       // 4 x 32 n-cols

    const uint32_t aoff = (uint32_t)((wm * 32 + (l & 15)) * 400 + ((l >> 4) & 1) * 16);
    const uint32_t boff = (uint32_t)((wn * 32 + (l & 7) + ((l >> 4) & 1) * 8) * 400
                                     + ((l >> 3) & 1) * 16);

    float acc[2][4][4];
#pragma unroll
    for (int mi = 0; mi < 2; ++mi)
#pragma unroll
        for (int nj = 0; nj < 4; ++nj)
#pragma unroll
            for (int r = 0; r < 4; ++r) acc[mi][nj][r] = 0.f;

    asm volatile("cp.async.wait_group 0;" ::: "memory");
    __syncthreads();

#pragma unroll 4
    for (int ks = 0; ks < 12; ++ks) {
        const uint32_t ko = ks * 32;
        uint32_t a[2][4], bq0[4], bq1[4];
        LDSM4(a[0], sb + OFF_AH + aoff + ko);
        LDSM4(a[1], sb + OFF_AH + aoff + 6400 + ko);
        LDSM4(bq0, sb + OFF_BH + boff + ko);
        LDSM4(bq1, sb + OFF_BH + boff + 6400 + ko);
#pragma unroll
        for (int mi = 0; mi < 2; ++mi) {
            MMA16816(acc[mi][0], a[mi], bq0[0], bq0[1]);
            MMA16816(acc[mi][1], a[mi], bq0[2], bq0[3]);
            MMA16816(acc[mi][2], a[mi], bq1[0], bq1[1]);
            MMA16816(acc[mi][3], a[mi], bq1[2], bq1[3]);
        }
    }

    // Epilogue: direct stores + bias
    const int nvalid = N_OUT - n0;
#pragma unroll
    for (int nj = 0; nj < 4; ++nj) {
        const int n = wn * 32 + nj * 8 + (l & 3) * 2;
        if (n < nvalid) {
            const float b0 = __ldg(fc_b + n0 + n);
            const float b1 = __ldg(fc_b + n0 + n + 1);
#pragma unroll
            for (int mi = 0; mi < 2; ++mi) {
                const int m = mg * 64 + wm * 32 + mi * 16 + (l >> 2);
                float* p0 = out + (size_t)m * N_OUT + n0 + n;
                float* p1 = out + (size_t)(m + 8) * N_OUT + n0 + n;
                *(float2*)p0 = make_float2(acc[mi][nj][0] + b0, acc[mi][nj][1] + b1);
                *(float2*)p1 = make_float2(acc[mi][nj][2] + b0, acc[mi][nj][3] + b1);
            }
        }
    }
}

// ---------------------------------------------------------------------------
extern "C" void kernel_launch(void* const* d_in, const int* in_sizes, int n_in,
                              void* d_out, int out_size) {
    const float* x          = (const float*)d_in[0];
    const float* conv_w     = (const float*)d_in[1];
    const float* bn_gamma   = (const float*)d_in[2];
    const float* bn_beta    = (const float*)d_in[3];
    const float* bn_mean    = (const float*)d_in[4];
    const float* bn_var     = (const float*)d_in[5];
    const float* in_proj_w  = (const float*)d_in[6];
    const float* in_proj_b  = (const float*)d_in[7];
    const float* out_proj_w = (const float*)d_in[8];
    const float* out_proj_b = (const float*)d_in[9];
    const float* fc_w       = (const float*)d_in[10];
    const float* fc_b       = (const float*)d_in[11];
    float* out = (float*)d_out;

    cudaFuncSetAttribute(fc_mma_kernel,
                         cudaFuncAttributeMaxDynamicSharedMemorySize, SMEM_FC);

    prep_b_kernel<<<(N_OUT * K_DIM + 255) / 256, 256>>>(fc_w);
    head_kernel<<<B_BATCH, 384>>>(x, conv_w, bn_gamma, bn_beta, bn_mean, bn_var,
                                  in_proj_w, in_proj_b, out_proj_w, out_proj_b);
    fc_mma_kernel<<<dim3(NT, 64), 256, SMEM_FC>>>(fc_b, out);
}

// round 9
// speedup vs baseline: 1.7392x; 1.0346x over previous
#include <cuda_runtime.h>
#include <cuda_fp16.h>
#include <cstdint>

// Problem constants
#define C_IN    256
#define S_SEQ   90
#define K_DIM   180
#define B_BATCH 4096
#define N_OUT   2086
#define MT      (B_BATCH / 128)        // 32 m-tile images (128 rows each)
#define NT      ((N_OUT + 127) / 128)  // 17 n-tile images
#define PITCH   200                    // row pitch in fp16 elems (400B, conflict-free ldmatrix)
#define TILE_E  (128 * PITCH)          // elems per 128-row tile image
#define PREP_BLOCKS ((N_OUT * K_DIM + 383) / 384)   // 978

// Tile images: [row][k] fp16, pitch 200. k in [180,200) stays ZERO (zero-init,
// never written); the GEMM consumes k in [0,192).
__device__ __align__(16) __half g_Ahi[MT * TILE_E];
__device__ __align__(16) __half g_Bhi[NT * TILE_E];

// ---------------------------------------------------------------------------
// head + prep_b fused: blocks [0,4096) do the attention head; blocks
// [4096, 4096+978) quantize fc_w into the B tile image.
// ---------------------------------------------------------------------------
__global__ __launch_bounds__(384) void head_kernel(
    const float* __restrict__ x,
    const float* __restrict__ conv_w,
    const float* __restrict__ bn_gamma, const float* __restrict__ bn_beta,
    const float* __restrict__ bn_mean,  const float* __restrict__ bn_var,
    const float* __restrict__ in_proj_w, const float* __restrict__ in_proj_b,
    const float* __restrict__ out_proj_w, const float* __restrict__ out_proj_b,
    const float* __restrict__ fc_w)
{
    // ---- prep_b blocks ----
    if (blockIdx.x >= B_BATCH) {
        int i = (blockIdx.x - B_BATCH) * 384 + threadIdx.x;
        if (i < N_OUT * K_DIM) {
            int n = i / K_DIM;
            int k = i - n * K_DIM;
            size_t idx = (size_t)(n >> 7) * TILE_E + (n & 127) * PITCH + k;
            g_Bhi[idx] = __float2half(fc_w[i]);
        }
        return;
    }

    __shared__ float sw0[C_IN], sw1[C_IN];
    __shared__ float part0[4][96], part1[4][96];
    __shared__ float sk0[S_SEQ], sk1[S_SEQ], sv0[S_SEQ], sv1[S_SEQ];
    __shared__ float sred[4];

    const int b   = blockIdx.x;
    const int tid = threadIdx.x;
    const int cc  = tid / 96;
    const int s   = tid - cc * 96;

    for (int i = tid; i < C_IN; i += 384) {
        sw0[i] = conv_w[i];
        sw1[i] = conv_w[C_IN + i];
    }
    __syncthreads();

    {
        float a0 = 0.f, a1 = 0.f;
        if (s < S_SEQ) {
            const float* xb = x + (size_t)b * (C_IN * S_SEQ) + cc * (64 * S_SEQ) + s;
            const float* w0 = sw0 + cc * 64;
            const float* w1 = sw1 + cc * 64;
#pragma unroll 16
            for (int c = 0; c < 64; ++c) {
                float xv = __ldg(xb + c * S_SEQ);
                a0 = fmaf(w0[c], xv, a0);
                a1 = fmaf(w1[c], xv, a1);
            }
        }
        part0[cc][s] = a0;
        part1[cc][s] = a1;
    }
    __syncthreads();

    float q0 = 0.f, q1 = 0.f;
    if (tid < S_SEQ) {
        float a0 = part0[0][tid] + part0[1][tid] + part0[2][tid] + part0[3][tid];
        float a1 = part1[0][tid] + part1[1][tid] + part1[2][tid] + part1[3][tid];
        float s0 = bn_gamma[0] * rsqrtf(bn_var[0] + 1e-5f);
        float s1 = bn_gamma[1] * rsqrtf(bn_var[1] + 1e-5f);
        float y0 = fmaf(a0, s0, bn_beta[0] - bn_mean[0] * s0);
        float y1 = fmaf(a1, s1, bn_beta[1] - bn_mean[1] * s1);
        q0       = fmaf(y0, in_proj_w[0],  fmaf(y1, in_proj_w[1],  in_proj_b[0]));
        q1       = fmaf(y0, in_proj_w[2],  fmaf(y1, in_proj_w[3],  in_proj_b[1]));
        sk0[tid] = fmaf(y0, in_proj_w[4],  fmaf(y1, in_proj_w[5],  in_proj_b[2]));
        sk1[tid] = fmaf(y0, in_proj_w[6],  fmaf(y1, in_proj_w[7],  in_proj_b[3]));
        sv0[tid] = fmaf(y0, in_proj_w[8],  fmaf(y1, in_proj_w[9],  in_proj_b[4]));
        sv1[tid] = fmaf(y0, in_proj_w[10], fmaf(y1, in_proj_w[11], in_proj_b[5]));
    }
    __syncthreads();

    if (tid < 64) {
        int h = tid >> 5, lane = tid & 31;
        const float* kk = h ? sk1 : sk0;
        float mx = -3.4e38f, mn = 3.4e38f;
        for (int j = lane; j < S_SEQ; j += 32) {
            float kv = kk[j];
            mx = fmaxf(mx, kv);
            mn = fminf(mn, kv);
        }
        for (int o = 16; o > 0; o >>= 1) {
            mx = fmaxf(mx, __shfl_xor_sync(0xffffffffu, mx, o));
            mn = fminf(mn, __shfl_xor_sync(0xffffffffu, mn, o));
        }
        if (lane == 0) { sred[h * 2] = mx; sred[h * 2 + 1] = mn; }
    }
    __syncthreads();

    if (tid < S_SEQ) {
        float m0 = fmaxf(q0 * sred[0], q0 * sred[1]);
        float m1 = fmaxf(q1 * sred[2], q1 * sred[3]);
        float d0 = 0.f, n0 = 0.f, d1 = 0.f, n1 = 0.f;
#pragma unroll 5
        for (int j = 0; j < S_SEQ; ++j) {
            float e0 = __expf(fmaf(q0, sk0[j], -m0));
            float e1 = __expf(fmaf(q1, sk1[j], -m1));
            d0 += e0; n0 = fmaf(e0, sv0[j], n0);
            d1 += e1; n1 = fmaf(e1, sv1[j], n1);
        }
        float o0 = n0 / d0, o1 = n1 / d1;
        float f0 = fmaf(o0, out_proj_w[0], fmaf(o1, out_proj_w[1], out_proj_b[0]));
        float f1 = fmaf(o0, out_proj_w[2], fmaf(o1, out_proj_w[3], out_proj_b[1]));
        size_t base = (size_t)(b >> 7) * TILE_E + (size_t)(b & 127) * PITCH;
        g_Ahi[base + tid]         = __float2half(f0);
        g_Ahi[base + S_SEQ + tid] = __float2half(f1);
    }
}

// ---------------------------------------------------------------------------
// FC GEMM: fp16 mma m16n8k16, fp32 accum. B-tile reuse over a 128-row m-sweep.
// Grid (17, 32): CTA stages B once + A in two 64-row halves (double-buffered).
// 256 threads (8 warps, 32x32 warp tile), 102.4KB smem -> 2 CTAs/SM.
// ---------------------------------------------------------------------------
#define OFF_A0 0          // 25600 B (64 rows x 400B)
#define OFF_A1 25600      // 25600 B
#define OFF_B  51200      // 51200 B (128 rows x 400B)
#define SMEM_FC 102400

__device__ __forceinline__ uint32_t smem_u32(const void* p) {
    uint32_t a;
    asm("{ .reg .u64 t; cvta.to.shared.u64 t, %1; cvt.u32.u64 %0, t; }"
        : "=r"(a) : "l"(p));
    return a;
}

#define CP16(dst, src)                                                         \
    asm volatile("cp.async.cg.shared.global [%0], [%1], 16;"                   \
                 :: "r"(dst), "l"(src))

#define LDSM4(r, addr)                                                         \
    asm volatile("ldmatrix.sync.aligned.m8n8.x4.shared.b16 {%0,%1,%2,%3}, [%4];" \
                 : "=r"((r)[0]), "=r"((r)[1]), "=r"((r)[2]), "=r"((r)[3])      \
                 : "r"(addr))

#define MMA16816(c, a, b0v, b1v)                                               \
    asm volatile(                                                              \
        "mma.sync.aligned.m16n8k16.row.col.f32.f16.f16.f32 "                   \
        "{%0,%1,%2,%3}, {%4,%5,%6,%7}, {%8,%9}, {%0,%1,%2,%3};"                \
        : "+f"((c)[0]), "+f"((c)[1]), "+f"((c)[2]), "+f"((c)[3])               \
        : "r"((a)[0]), "r"((a)[1]), "r"((a)[2]), "r"((a)[3]),                  \
          "r"(b0v), "r"(b1v))

__global__ __launch_bounds__(256, 2) void fc_mma_kernel(
    const float* __restrict__ fc_b, float* __restrict__ out)
{
    extern __shared__ char sm[];
    const uint32_t sb = smem_u32(sm);
    const int tid = threadIdx.x;
    const int wid = tid >> 5;
    const int l   = tid & 31;
    const int nt  = blockIdx.x;          // 0..16
    const int mg2 = blockIdx.y;          // 0..31 (one 128-row A image)
    const int n0  = nt * 128;

    // Stage: group 0 = A half0 + B; group 1 = A half1
    {
        const float4* gA = (const float4*)(g_Ahi + (size_t)mg2 * TILE_E);
        const float4* gB = (const float4*)(g_Bhi + (size_t)nt * TILE_E);
        for (int i = tid; i < 1600; i += 256)
            CP16(sb + OFF_A0 + i * 16, gA + i);
        for (int i = tid; i < 3200; i += 256)
            CP16(sb + OFF_B + i * 16, gB + i);
        asm volatile("cp.async.commit_group;" ::: "memory");
        for (int i = tid; i < 1600; i += 256)
            CP16(sb + OFF_A1 + i * 16, gA + 1600 + i);
        asm volatile("cp.async.commit_group;" ::: "memory");
    }

    const int wm = wid & 1;        // 2 x 32 m-rows
    const int wn = wid >> 1;       // 4 x 32 n-cols

    const uint32_t aoff = (uint32_t)((wm * 32 + (l & 15)) * 400 + ((l >> 4) & 1) * 16);
    const uint32_t boff = (uint32_t)((wn * 32 + (l & 7) + ((l >> 4) & 1) * 8) * 400
                                     + ((l >> 3) & 1) * 16);
    const int nvalid = N_OUT - n0;

    // bias regs (shared by both halves)
    float fb0[4], fb1[4];
#pragma unroll
    for (int nj = 0; nj < 4; ++nj) {
        int n = n0 + wn * 32 + nj * 8 + (l & 3) * 2;
        fb0[nj] = (n < N_OUT)     ? __ldg(fc_b + n)     : 0.f;
        fb1[nj] = (n + 1 < N_OUT) ? __ldg(fc_b + n + 1) : 0.f;
    }

#pragma unroll
    for (int half = 0; half < 2; ++half) {
        if (half == 0)
            asm volatile("cp.async.wait_group 1;" ::: "memory");
        else
            asm volatile("cp.async.wait_group 0;" ::: "memory");
        __syncthreads();

        const uint32_t Ab = sb + (half ? OFF_A1 : OFF_A0) + aoff;

        float acc[2][4][4];
#pragma unroll
        for (int mi = 0; mi < 2; ++mi)
#pragma unroll
            for (int nj = 0; nj < 4; ++nj)
#pragma unroll
                for (int r = 0; r < 4; ++r) acc[mi][nj][r] = 0.f;

#pragma unroll 4
        for (int ks = 0; ks < 12; ++ks) {
            const uint32_t ko = ks * 32;
            uint32_t a[2][4], bq0[4], bq1[4];
            LDSM4(a[0], Ab + ko);
            LDSM4(a[1], Ab + 6400 + ko);
            LDSM4(bq0, sb + OFF_B + boff + ko);
            LDSM4(bq1, sb + OFF_B + boff + 6400 + ko);
#pragma unroll
            for (int mi = 0; mi < 2; ++mi) {
                MMA16816(acc[mi][0], a[mi], bq0[0], bq0[1]);
                MMA16816(acc[mi][1], a[mi], bq0[2], bq0[3]);
                MMA16816(acc[mi][2], a[mi], bq1[0], bq1[1]);
                MMA16816(acc[mi][3], a[mi], bq1[2], bq1[3]);
            }
        }

        // Epilogue for this half (overlaps the other CTA's work / A1 arrival)
#pragma unroll
        for (int nj = 0; nj < 4; ++nj) {
            const int n = wn * 32 + nj * 8 + (l & 3) * 2;
            if (n < nvalid) {
#pragma unroll
                for (int mi = 0; mi < 2; ++mi) {
                    const int m = mg2 * 128 + half * 64 + wm * 32 + mi * 16 + (l >> 2);
                    float* p0 = out + (size_t)m * N_OUT + n0 + n;
                    float* p1 = out + (size_t)(m + 8) * N_OUT + n0 + n;
                    *(float2*)p0 = make_float2(acc[mi][nj][0] + fb0[nj],
                                               acc[mi][nj][1] + fb1[nj]);
                    *(float2*)p1 = make_float2(acc[mi][nj][2] + fb0[nj],
                                               acc[mi][nj][3] + fb1[nj]);
                }
            }
        }
    }
}

// ---------------------------------------------------------------------------
extern "C" void kernel_launch(void* const* d_in, const int* in_sizes, int n_in,
                              void* d_out, int out_size) {
    const float* x          = (const float*)d_in[0];
    const float* conv_w     = (const float*)d_in[1];
    const float* bn_gamma   = (const float*)d_in[2];
    const float* bn_beta    = (const float*)d_in[3];
    const float* bn_mean    = (const float*)d_in[4];
    const float* bn_var     = (const float*)d_in[5];
    const float* in_proj_w  = (const float*)d_in[6];
    const float* in_proj_b  = (const float*)d_in[7];
    const float* out_proj_w = (const float*)d_in[8];
    const float* out_proj_b = (const float*)d_in[9];
    const float* fc_w       = (const float*)d_in[10];
    const float* fc_b       = (const float*)d_in[11];
    float* out = (float*)d_out;

    cudaFuncSetAttribute(fc_mma_kernel,
                         cudaFuncAttributeMaxDynamicSharedMemorySize, SMEM_FC);

    head_kernel<<<B_BATCH + PREP_BLOCKS, 384>>>(
        x, conv_w, bn_gamma, bn_beta, bn_mean, bn_var,
        in_proj_w, in_proj_b, out_proj_w, out_proj_b, fc_w);
    fc_mma_kernel<<<dim3(NT, MT), 256, SMEM_FC>>>(fc_b, out);
}

// round 10
// speedup vs baseline: 1.7701x; 1.0178x over previous
#include <cuda_runtime.h>
#include <cuda_fp16.h>
#include <cstdint>

// Problem constants
#define C_IN    256
#define S_SEQ   90
#define K_DIM   180
#define B_BATCH 4096
#define N_OUT   2086
#define MT      (B_BATCH / 128)        // 32 m-tile images (128 rows each)
#define NT      ((N_OUT + 127) / 128)  // 17 n-tile images
#define PITCH   200                    // row pitch in fp16 elems (400B, conflict-free ldmatrix)
#define TILE_E  (128 * PITCH)          // elems per 128-row tile image
#define PREP_BLOCKS ((N_OUT * K_DIM + 383) / 384)   // 978

// Tile images: [row][k] fp16, pitch 200. k in [180,200) stays ZERO (zero-init,
// never written); the GEMM consumes k in [0,192).
__device__ __align__(16) __half g_Ahi[MT * TILE_E];
__device__ __align__(16) __half g_Bhi[NT * TILE_E];

__device__ __forceinline__ float ex2f(float x) {
    float r;
    asm("ex2.approx.f32 %0, %1;" : "=f"(r) : "f"(x));
    return r;
}

// ---------------------------------------------------------------------------
// head + prep_b fused: blocks [0,4096) = attention head; blocks
// [4096, 4096+978) quantize fc_w into the B tile image.
//
// Head structure (384 threads):
//  conv:    thread (cc in [0,8), u in [0,45)) does 32 channels x {s=2u, 2u+1}
//           via float2 loads; partials in cpart[16][48] (float2).
//  qkv:     threads 0..89 reduce 8 partials, BN, QKV projection -> smem rows.
//  softmax: all threads; (g in [0,4), s in [0,96)) does ~23 of 90 keys,
//           partial (d,n) per head -> 4-way smem reduce. Unshifted exact
//           softmax via ex2 (|q.k| small; no overflow possible).
//  final:   threads 0..89 combine, out_proj, fp16 store to A tile image.
// ---------------------------------------------------------------------------
__global__ __launch_bounds__(384) void head_kernel(
    const float* __restrict__ x,
    const float* __restrict__ conv_w,
    const float* __restrict__ bn_gamma, const float* __restrict__ bn_beta,
    const float* __restrict__ bn_mean,  const float* __restrict__ bn_var,
    const float* __restrict__ in_proj_w, const float* __restrict__ in_proj_b,
    const float* __restrict__ out_proj_w, const float* __restrict__ out_proj_b,
    const float* __restrict__ fc_w)
{
    // ---- prep_b blocks ----
    if (blockIdx.x >= B_BATCH) {
        int i = (blockIdx.x - B_BATCH) * 384 + threadIdx.x;
        if (i < N_OUT * K_DIM) {
            int n = i / K_DIM;
            int k = i - n * K_DIM;
            size_t idx = (size_t)(n >> 7) * TILE_E + (n & 127) * PITCH + k;
            g_Bhi[idx] = __float2half(fc_w[i]);
        }
        return;
    }

    __shared__ float sw0[C_IN], sw1[C_IN];
    __shared__ float2 cpart[16][48];          // conv partials (head0: rows 0-7, head1: 8-15)
    __shared__ float sk0[S_SEQ], sk1[S_SEQ], sv0[S_SEQ], sv1[S_SEQ];
    __shared__ float sq0[S_SEQ], sq1[S_SEQ];  // pre-scaled by log2(e)
    __shared__ float pd0[4][96], pn0[4][96], pd1[4][96], pn1[4][96];

    const int b   = blockIdx.x;
    const int tid = threadIdx.x;

    if (tid < C_IN) {
        sw0[tid] = conv_w[tid];
        sw1[tid] = conv_w[C_IN + tid];
    }
    __syncthreads();

    // ---- conv: float2 loads, 32 channels per thread ----
    {
        const int cc = tid / 48;        // 0..7
        const int u  = tid - cc * 48;   // 0..47 (u<45 active)
        float2 a0 = make_float2(0.f, 0.f);
        float2 a1 = make_float2(0.f, 0.f);
        if (u < 45) {
            const float* xb = x + (size_t)b * (C_IN * S_SEQ) + cc * (32 * S_SEQ);
            const float* w0 = sw0 + cc * 32;
            const float* w1 = sw1 + cc * 32;
#pragma unroll 8
            for (int c = 0; c < 32; ++c) {
                float2 xv = __ldg((const float2*)(xb + c * S_SEQ) + u);
                float wa = w0[c], wb = w1[c];
                a0.x = fmaf(wa, xv.x, a0.x);
                a0.y = fmaf(wa, xv.y, a0.y);
                a1.x = fmaf(wb, xv.x, a1.x);
                a1.y = fmaf(wb, xv.y, a1.y);
            }
        }
        cpart[cc][u]     = a0;
        cpart[8 + cc][u] = a1;
    }
    __syncthreads();

    // ---- qkv: threads 0..89 ----
    if (tid < S_SEQ) {
        const int half = tid & 1;
        const int uu   = tid >> 1;
        float a0 = 0.f, a1 = 0.f;
#pragma unroll
        for (int j = 0; j < 8; ++j) {
            float2 v0 = cpart[j][uu];
            float2 v1 = cpart[8 + j][uu];
            a0 += half ? v0.y : v0.x;
            a1 += half ? v1.y : v1.x;
        }
        float s0 = bn_gamma[0] * rsqrtf(bn_var[0] + 1e-5f);
        float s1 = bn_gamma[1] * rsqrtf(bn_var[1] + 1e-5f);
        float y0 = fmaf(a0, s0, bn_beta[0] - bn_mean[0] * s0);
        float y1 = fmaf(a1, s1, bn_beta[1] - bn_mean[1] * s1);
        const float L2E = 1.44269504f;
        sq0[tid] = L2E * fmaf(y0, in_proj_w[0],  fmaf(y1, in_proj_w[1],  in_proj_b[0]));
        sq1[tid] = L2E * fmaf(y0, in_proj_w[2],  fmaf(y1, in_proj_w[3],  in_proj_b[1]));
        sk0[tid] = fmaf(y0, in_proj_w[4],  fmaf(y1, in_proj_w[5],  in_proj_b[2]));
        sk1[tid] = fmaf(y0, in_proj_w[6],  fmaf(y1, in_proj_w[7],  in_proj_b[3]));
        sv0[tid] = fmaf(y0, in_proj_w[8],  fmaf(y1, in_proj_w[9],  in_proj_b[4]));
        sv1[tid] = fmaf(y0, in_proj_w[10], fmaf(y1, in_proj_w[11], in_proj_b[5]));
    }
    __syncthreads();

    // ---- softmax partials: (g, s); j in [g*23, min(g*23+23, 90)) ----
    {
        const int g = tid / 96;         // 0..3
        const int s = tid - g * 96;     // 0..95 (s<90 active)
        float d0 = 0.f, n0 = 0.f, d1 = 0.f, n1 = 0.f;
        if (s < S_SEQ) {
            const float q0 = sq0[s];
            const float q1 = sq1[s];
            const int jlo = g * 23;
            const int jhi = (g == 3) ? S_SEQ : jlo + 23;
#pragma unroll 23
            for (int j = jlo; j < jhi; ++j) {
                float e0 = ex2f(q0 * sk0[j]);
                float e1 = ex2f(q1 * sk1[j]);
                d0 += e0; n0 = fmaf(e0, sv0[j], n0);
                d1 += e1; n1 = fmaf(e1, sv1[j], n1);
            }
        }
        pd0[g][s] = d0; pn0[g][s] = n0;
        pd1[g][s] = d1; pn1[g][s] = n1;
    }
    __syncthreads();

    // ---- final: combine partials, out_proj, store fp16 A tile ----
    if (tid < S_SEQ) {
        float d0 = pd0[0][tid] + pd0[1][tid] + pd0[2][tid] + pd0[3][tid];
        float n0 = pn0[0][tid] + pn0[1][tid] + pn0[2][tid] + pn0[3][tid];
        float d1 = pd1[0][tid] + pd1[1][tid] + pd1[2][tid] + pd1[3][tid];
        float n1 = pn1[0][tid] + pn1[1][tid] + pn1[2][tid] + pn1[3][tid];
        float o0 = n0 / d0, o1 = n1 / d1;
        float f0 = fmaf(o0, out_proj_w[0], fmaf(o1, out_proj_w[1], out_proj_b[0]));
        float f1 = fmaf(o0, out_proj_w[2], fmaf(o1, out_proj_w[3], out_proj_b[1]));
        size_t base = (size_t)(b >> 7) * TILE_E + (size_t)(b & 127) * PITCH;
        g_Ahi[base + tid]         = __float2half(f0);
        g_Ahi[base + S_SEQ + tid] = __float2half(f1);
    }
}

// ---------------------------------------------------------------------------
// FC GEMM (unchanged R9 winner): fp16 mma m16n8k16, fp32 accum, B-tile reuse
// over a 128-row m-sweep. Grid (17, 32), 256 threads, 102.4KB smem, 2 CTAs/SM.
// ---------------------------------------------------------------------------
#define OFF_A0 0          // 25600 B (64 rows x 400B)
#define OFF_A1 25600      // 25600 B
#define OFF_B  51200      // 51200 B (128 rows x 400B)
#define SMEM_FC 102400

__device__ __forceinline__ uint32_t smem_u32(const void* p) {
    uint32_t a;
    asm("{ .reg .u64 t; cvta.to.shared.u64 t, %1; cvt.u32.u64 %0, t; }"
        : "=r"(a) : "l"(p));
    return a;
}

#define CP16(dst, src)                                                         \
    asm volatile("cp.async.cg.shared.global [%0], [%1], 16;"                   \
                 :: "r"(dst), "l"(src))

#define LDSM4(r, addr)                                                         \
    asm volatile("ldmatrix.sync.aligned.m8n8.x4.shared.b16 {%0,%1,%2,%3}, [%4];" \
                 : "=r"((r)[0]), "=r"((r)[1]), "=r"((r)[2]), "=r"((r)[3])      \
                 : "r"(addr))

#define MMA16816(c, a, b0v, b1v)                                               \
    asm volatile(                                                              \
        "mma.sync.aligned.m16n8k16.row.col.f32.f16.f16.f32 "                   \
        "{%0,%1,%2,%3}, {%4,%5,%6,%7}, {%8,%9}, {%0,%1,%2,%3};"                \
        : "+f"((c)[0]), "+f"((c)[1]), "+f"((c)[2]), "+f"((c)[3])               \
        : "r"((a)[0]), "r"((a)[1]), "r"((a)[2]), "r"((a)[3]),                  \
          "r"(b0v), "r"(b1v))

__global__ __launch_bounds__(256, 2) void fc_mma_kernel(
    const float* __restrict__ fc_b, float* __restrict__ out)
{
    extern __shared__ char sm[];
    const uint32_t sb = smem_u32(sm);
    const int tid = threadIdx.x;
    const int wid = tid >> 5;
    const int l   = tid & 31;
    const int nt  = blockIdx.x;          // 0..16
    const int mg2 = blockIdx.y;          // 0..31 (one 128-row A image)
    const int n0  = nt * 128;

    // Stage: group 0 = A half0 + B; group 1 = A half1
    {
        const float4* gA = (const float4*)(g_Ahi + (size_t)mg2 * TILE_E);
        const float4* gB = (const float4*)(g_Bhi + (size_t)nt * TILE_E);
        for (int i = tid; i < 1600; i += 256)
            CP16(sb + OFF_A0 + i * 16, gA + i);
        for (int i = tid; i < 3200; i += 256)
            CP16(sb + OFF_B + i * 16, gB + i);
        asm volatile("cp.async.commit_group;" ::: "memory");
        for (int i = tid; i < 1600; i += 256)
            CP16(sb + OFF_A1 + i * 16, gA + 1600 + i);
        asm volatile("cp.async.commit_group;" ::: "memory");
    }

    const int wm = wid & 1;        // 2 x 32 m-rows
    const int wn = wid >> 1;       // 4 x 32 n-cols

    const uint32_t aoff = (uint32_t)((wm * 32 + (l & 15)) * 400 + ((l >> 4) & 1) * 16);
    const uint32_t boff = (uint32_t)((wn * 32 + (l & 7) + ((l >> 4) & 1) * 8) * 400
                                     + ((l >> 3) & 1) * 16);
    const int nvalid = N_OUT - n0;

    // bias regs (shared by both halves)
    float fb0[4], fb1[4];
#pragma unroll
    for (int nj = 0; nj < 4; ++nj) {
        int n = n0 + wn * 32 + nj * 8 + (l & 3) * 2;
        fb0[nj] = (n < N_OUT)     ? __ldg(fc_b + n)     : 0.f;
        fb1[nj] = (n + 1 < N_OUT) ? __ldg(fc_b + n + 1) : 0.f;
    }

#pragma unroll
    for (int half = 0; half < 2; ++half) {
        if (half == 0)
            asm volatile("cp.async.wait_group 1;" ::: "memory");
        else
            asm volatile("cp.async.wait_group 0;" ::: "memory");
        __syncthreads();

        const uint32_t Ab = sb + (half ? OFF_A1 : OFF_A0) + aoff;

        float acc[2][4][4];
#pragma unroll
        for (int mi = 0; mi < 2; ++mi)
#pragma unroll
            for (int nj = 0; nj < 4; ++nj)
#pragma unroll
                for (int r = 0; r < 4; ++r) acc[mi][nj][r] = 0.f;

#pragma unroll 4
        for (int ks = 0; ks < 12; ++ks) {
            const uint32_t ko = ks * 32;
            uint32_t a[2][4], bq0[4], bq1[4];
            LDSM4(a[0], Ab + ko);
            LDSM4(a[1], Ab + 6400 + ko);
            LDSM4(bq0, sb + OFF_B + boff + ko);
            LDSM4(bq1, sb + OFF_B + boff + 6400 + ko);
#pragma unroll
            for (int mi = 0; mi < 2; ++mi) {
                MMA16816(acc[mi][0], a[mi], bq0[0], bq0[1]);
                MMA16816(acc[mi][1], a[mi], bq0[2], bq0[3]);
                MMA16816(acc[mi][2], a[mi], bq1[0], bq1[1]);
                MMA16816(acc[mi][3], a[mi], bq1[2], bq1[3]);
            }
        }

        // Epilogue for this half
#pragma unroll
        for (int nj = 0; nj < 4; ++nj) {
            const int n = wn * 32 + nj * 8 + (l & 3) * 2;
            if (n < nvalid) {
#pragma unroll
                for (int mi = 0; mi < 2; ++mi) {
                    const int m = mg2 * 128 + half * 64 + wm * 32 + mi * 16 + (l >> 2);
                    float* p0 = out + (size_t)m * N_OUT + n0 + n;
                    float* p1 = out + (size_t)(m + 8) * N_OUT + n0 + n;
                    *(float2*)p0 = make_float2(acc[mi][nj][0] + fb0[nj],
                                               acc[mi][nj][1] + fb1[nj]);
                    *(float2*)p1 = make_float2(acc[mi][nj][2] + fb0[nj],
                                               acc[mi][nj][3] + fb1[nj]);
                }
            }
        }
    }
}

// ---------------------------------------------------------------------------
extern "C" void kernel_launch(void* const* d_in, const int* in_sizes, int n_in,
                              void* d_out, int out_size) {
    const float* x          = (const float*)d_in[0];
    const float* conv_w     = (const float*)d_in[1];
    const float* bn_gamma   = (const float*)d_in[2];
    const float* bn_beta    = (const float*)d_in[3];
    const float* bn_mean    = (const float*)d_in[4];
    const float* bn_var     = (const float*)d_in[5];
    const float* in_proj_w  = (const float*)d_in[6];
    const float* in_proj_b  = (const float*)d_in[7];
    const float* out_proj_w = (const float*)d_in[8];
    const float* out_proj_b = (const float*)d_in[9];
    const float* fc_w       = (const float*)d_in[10];
    const float* fc_b       = (const float*)d_in[11];
    float* out = (float*)d_out;

    cudaFuncSetAttribute(fc_mma_kernel,
                         cudaFuncAttributeMaxDynamicSharedMemorySize, SMEM_FC);

    head_kernel<<<B_BATCH + PREP_BLOCKS, 384>>>(
        x, conv_w, bn_gamma, bn_beta, bn_mean, bn_var,
        in_proj_w, in_proj_b, out_proj_w, out_proj_b, fc_w);
    fc_mma_kernel<<<dim3(NT, MT), 256, SMEM_FC>>>(fc_b, out);
}